// round 12
// baseline (speedup 1.0000x reference)
#include <cuda_runtime.h>
#include <cstdint>

// Problem constants (fixed by the reference: n=4096, d=2048, num_ids=256)
#define N_ROWS 4096
#define DCOLS  2048
#define ROW_F4 (DCOLS / 4)   // 512 float4 per row
#define RPB    8             // rows per block
#define P2_BLOCKS (8192 / RPB)   // 1024  (pair2 first: scans overlap copies)
#define P1_BLOCKS (4096 / RPB)   // 512

// ---------------------------------------------------------------------------
// Bit-exact JAX threefry-2x32 (20 rounds)
// ---------------------------------------------------------------------------
__device__ __forceinline__ void threefry2x32(uint32_t k0, uint32_t k1,
                                             uint32_t c0, uint32_t c1,
                                             uint32_t& o0, uint32_t& o1) {
    const uint32_t ks2 = k0 ^ k1 ^ 0x1BD11BDAu;
    uint32_t x0 = c0 + k0;
    uint32_t x1 = c1 + k1;
#define TF_ROUND(r) { x0 += x1; x1 = (x1 << (r)) | (x1 >> (32 - (r))); x1 ^= x0; }
    TF_ROUND(13) TF_ROUND(15) TF_ROUND(26) TF_ROUND(6)
    x0 += k1;  x1 += ks2 + 1u;
    TF_ROUND(17) TF_ROUND(29) TF_ROUND(16) TF_ROUND(24)
    x0 += ks2; x1 += k0 + 2u;
    TF_ROUND(13) TF_ROUND(15) TF_ROUND(26) TF_ROUND(6)
    x0 += k0;  x1 += k1 + 3u;
    TF_ROUND(17) TF_ROUND(29) TF_ROUND(16) TF_ROUND(24)
    x0 += k1;  x1 += ks2 + 4u;
    TF_ROUND(13) TF_ROUND(15) TF_ROUND(26) TF_ROUND(6)
    x0 += ks2; x1 += k0 + 5u;
#undef TF_ROUND
    o0 = x0; o1 = x1;
}

// jax.random.uniform f32: bitcast(0x3F800000 | (bits >> 9)) - 1
__device__ __forceinline__ float bits_to_uniform(uint32_t b) {
    return __uint_as_float(0x3F800000u | (b >> 9)) - 1.0f;
}

// Partitionable threefry random bits for element i: counter=(0,i), out = o0^o1.
__device__ __forceinline__ uint32_t jax_bits32(uint32_t key_lo, uint32_t i) {
    uint32_t o0, o1;
    threefry2x32(0u, key_lo, 0u, i, o0, o1);
    return o0 ^ o1;
}

// Copy two rows (512 float4 each) with 256 threads; 4 independent loads
// batched before any store for MLP.
__device__ __forceinline__ void copy2(const float4* __restrict__ sA,
                                      const float4* __restrict__ sB,
                                      float4* __restrict__ dA,
                                      float4* __restrict__ dB, int t) {
    const float4 a0 = __ldg(sA + t);
    const float4 a1 = __ldg(sA + t + 256);
    const float4 b0 = __ldg(sB + t);
    const float4 b1 = __ldg(sB + t + 256);
    __stcs(dA + t,       a0); __stcs(dA + t + 256, a1);
    __stcs(dB + t,       b0); __stcs(dB + t + 256, b1);
}

// ---------------------------------------------------------------------------
// fused_kernel, single launch, 1536 blocks x 256 threads.
//   Blocks [0, 1024):    pair2. Block q owns pair2 rows [q*8, q*8+8) of 8192.
//       Prologue: same-identity counts for the 8 rows via one pass over
//       targets (16 KB, L2-hot; 8 compares per loaded value), REDUX warp
//       reduction, then partitionable-threefry indices. Then gather-copy.
//   Blocks [1024, 1536): pair1. Block p owns input rows [p*8, p*8+8); each
//       float4 loaded once, stored to pair1 rows r and r+4096. First 16
//       blocks also write y.
// ---------------------------------------------------------------------------
__global__ void __launch_bounds__(256)
fused_kernel(const float4* __restrict__ in,
             const int* __restrict__ targets,
             float4* __restrict__ out,
             float* __restrict__ y_out) {
    const int t = threadIdx.x;
    const int b = blockIdx.x;

    if (b < P2_BLOCKS) {
        // ---------------- pair2 ----------------
        const int row0 = b * RPB;                  // pair2 row in [0, 8192)

        __shared__ int s_tgt[RPB];
        __shared__ int s_cnt[RPB];
        __shared__ int s_src[RPB];
        if (t < RPB) {
            s_tgt[t] = targets[(row0 + t) & (N_ROWS - 1)];
            s_cnt[t] = 0;
        }
        __syncthreads();

        // Counts: one coalesced pass over targets, 8 compares per value
        int c[RPB];
        #pragma unroll
        for (int j = 0; j < RPB; ++j) c[j] = 0;
        const int t0 = s_tgt[0], t1 = s_tgt[1], t2 = s_tgt[2], t3 = s_tgt[3];
        const int t4 = s_tgt[4], t5 = s_tgt[5], t6 = s_tgt[6], t7 = s_tgt[7];
        #pragma unroll
        for (int k = 0; k < N_ROWS / 256; ++k) {   // 16 L2-hot loads
            const int v = __ldg(&targets[k * 256 + t]);
            c[0] += (v == t0); c[1] += (v == t1); c[2] += (v == t2); c[3] += (v == t3);
            c[4] += (v == t4); c[5] += (v == t5); c[6] += (v == t6); c[7] += (v == t7);
        }
        #pragma unroll
        for (int j = 0; j < RPB; ++j)
            c[j] = __reduce_add_sync(0xFFFFFFFFu, c[j]);   // REDUX.SUM
        if ((t & 31) == 0) {
            #pragma unroll
            for (int j = 0; j < RPB; ++j) atomicAdd(&s_cnt[j], c[j]);
        }
        __syncthreads();

        if (t < RPB) {
            const int r  = row0 + t;
            const int i  = r & (N_ROWS - 1);       // element index for PRNG
            const int pc = s_cnt[t];
            int      cnt;
            uint32_t key;
            if (r < N_ROWS) { cnt = pc; key = 1u; }     // positives: key(1)
            else {
                cnt = N_ROWS - pc;
                if (cnt < 1) cnt = 1;
                key = 2u;                                // negatives: key(2)
            }
            const float u = bits_to_uniform(jax_bits32(key, (uint32_t)i));
            int idx = (int)(u * (float)cnt);             // f32 mul + trunc
            if (idx > cnt - 1) idx = cnt - 1;
            s_src[t] = idx;
        }
        __syncthreads();

        float4* base = out + (size_t)2 * N_ROWS * ROW_F4;  // start of pair2
        #pragma unroll
        for (int rp = 0; rp < RPB / 2; ++rp) {
            const int r0 = row0 + rp * 2;
            copy2(in + (size_t)s_src[rp * 2]     * ROW_F4,
                  in + (size_t)s_src[rp * 2 + 1] * ROW_F4,
                  base + (size_t)r0       * ROW_F4,
                  base + (size_t)(r0 + 1) * ROW_F4, t);
        }
    } else {
        // ---------------- pair1: dual store ----------------
        const int p    = b - P2_BLOCKS;
        const int row0 = p * RPB;                  // input row in [0, 4096)
        #pragma unroll
        for (int rr = 0; rr < RPB; rr += 2) {
            const int r0 = row0 + rr;
            const int r1 = r0 + 1;
            const float4* s0 = in + (size_t)r0 * ROW_F4;
            const float4* s1 = in + (size_t)r1 * ROW_F4;
            const float4 a0 = __ldg(s0 + t);
            const float4 a1 = __ldg(s0 + t + 256);
            const float4 b0 = __ldg(s1 + t);
            const float4 b1 = __ldg(s1 + t + 256);
            float4* dA0 = out + (size_t)r0 * ROW_F4;
            float4* dB0 = out + (size_t)(r0 + N_ROWS) * ROW_F4;
            float4* dA1 = out + (size_t)r1 * ROW_F4;
            float4* dB1 = out + (size_t)(r1 + N_ROWS) * ROW_F4;
            __stcs(dA0 + t,       a0); __stcs(dA0 + t + 256, a1);
            __stcs(dB0 + t,       a0); __stcs(dB0 + t + 256, a1);
            __stcs(dA1 + t,       b0); __stcs(dA1 + t + 256, b1);
            __stcs(dB1 + t,       b0); __stcs(dB1 + t + 256, b1);
        }
        // y = [1]*n ++ [0]*n : 512 floats per block for the first 16 blocks
        if (p < 16) {
            const int base = p * 512;
            y_out[base + t]       = (base + t       < N_ROWS) ? 1.0f : 0.0f;
            y_out[base + 256 + t] = (base + 256 + t < N_ROWS) ? 1.0f : 0.0f;
        }
    }
}

// ---------------------------------------------------------------------------
// kernel_launch: inputs = d_in[0] (f32 4096x2048), targets = d_in[1] (i32 4096)
// out layout (flat f32): pair1 [2n*d] | pair2 [2n*d] | y [2n]
// ---------------------------------------------------------------------------
extern "C" void kernel_launch(void* const* d_in, const int* in_sizes, int n_in,
                              void* d_out, int out_size) {
    (void)in_sizes; (void)n_in; (void)out_size;
    const float* inputs  = (const float*)d_in[0];
    const int*   targets = (const int*)d_in[1];
    float*       out     = (float*)d_out;
    float*       y       = out + (size_t)4 * N_ROWS * DCOLS;  // after pair1|pair2

    fused_kernel<<<P2_BLOCKS + P1_BLOCKS, 256>>>(
        (const float4*)inputs, targets, (float4*)out, y);
}

// round 13
// speedup vs baseline: 1.0067x; 1.0067x over previous
#include <cuda_runtime.h>
#include <cstdint>

// Problem constants (fixed by the reference: n=4096, d=2048, num_ids=256)
#define N_ROWS 4096
#define DCOLS  2048
#define ROW_F4 (DCOLS / 4)   // 512 float4 per row
#define RPB    8             // rows per block
#define P2_BLOCKS (8192 / RPB)   // 1024  (pair2 first: scans overlap copies)
#define P1_BLOCKS (4096 / RPB)   // 512

// ---------------------------------------------------------------------------
// Bit-exact JAX threefry-2x32 (20 rounds)
// ---------------------------------------------------------------------------
__device__ __forceinline__ void threefry2x32(uint32_t k0, uint32_t k1,
                                             uint32_t c0, uint32_t c1,
                                             uint32_t& o0, uint32_t& o1) {
    const uint32_t ks2 = k0 ^ k1 ^ 0x1BD11BDAu;
    uint32_t x0 = c0 + k0;
    uint32_t x1 = c1 + k1;
#define TF_ROUND(r) { x0 += x1; x1 = (x1 << (r)) | (x1 >> (32 - (r))); x1 ^= x0; }
    TF_ROUND(13) TF_ROUND(15) TF_ROUND(26) TF_ROUND(6)
    x0 += k1;  x1 += ks2 + 1u;
    TF_ROUND(17) TF_ROUND(29) TF_ROUND(16) TF_ROUND(24)
    x0 += ks2; x1 += k0 + 2u;
    TF_ROUND(13) TF_ROUND(15) TF_ROUND(26) TF_ROUND(6)
    x0 += k0;  x1 += k1 + 3u;
    TF_ROUND(17) TF_ROUND(29) TF_ROUND(16) TF_ROUND(24)
    x0 += k1;  x1 += ks2 + 4u;
    TF_ROUND(13) TF_ROUND(15) TF_ROUND(26) TF_ROUND(6)
    x0 += ks2; x1 += k0 + 5u;
#undef TF_ROUND
    o0 = x0; o1 = x1;
}

// jax.random.uniform f32: bitcast(0x3F800000 | (bits >> 9)) - 1
__device__ __forceinline__ float bits_to_uniform(uint32_t b) {
    return __uint_as_float(0x3F800000u | (b >> 9)) - 1.0f;
}

// Partitionable threefry random bits for element i: counter=(0,i), out = o0^o1.
__device__ __forceinline__ uint32_t jax_bits32(uint32_t key_lo, uint32_t i) {
    uint32_t o0, o1;
    threefry2x32(0u, key_lo, 0u, i, o0, o1);
    return o0 ^ o1;
}

// Copy two rows (512 float4 each) with 256 threads; 4 independent loads
// batched before any store for MLP.
__device__ __forceinline__ void copy2(const float4* __restrict__ sA,
                                      const float4* __restrict__ sB,
                                      float4* __restrict__ dA,
                                      float4* __restrict__ dB, int t) {
    const float4 a0 = __ldg(sA + t);
    const float4 a1 = __ldg(sA + t + 256);
    const float4 b0 = __ldg(sB + t);
    const float4 b1 = __ldg(sB + t + 256);
    __stcs(dA + t,       a0); __stcs(dA + t + 256, a1);
    __stcs(dB + t,       b0); __stcs(dB + t + 256, b1);
}

// ---------------------------------------------------------------------------
// fused_kernel, single launch, 1536 blocks x 256 threads.
//   Blocks [0, 1024):    pair2. Block q owns pair2 rows [q*8, q*8+8) of 8192.
//       Prologue: same-identity counts for the 8 rows via one pass over
//       targets (16 KB, L2-hot; 8 compares per loaded value), REDUX warp
//       reduction, then partitionable-threefry indices. Then gather-copy.
//   Blocks [1024, 1536): pair1. Block p owns input rows [p*8, p*8+8); each
//       float4 loaded once, stored to pair1 rows r and r+4096. First 16
//       blocks also write y.
// ---------------------------------------------------------------------------
__global__ void __launch_bounds__(256)
fused_kernel(const float4* __restrict__ in,
             const int* __restrict__ targets,
             float4* __restrict__ out,
             float* __restrict__ y_out) {
    const int t = threadIdx.x;
    const int b = blockIdx.x;

    if (b < P2_BLOCKS) {
        // ---------------- pair2 ----------------
        const int row0 = b * RPB;                  // pair2 row in [0, 8192)

        __shared__ int s_tgt[RPB];
        __shared__ int s_cnt[RPB];
        __shared__ int s_src[RPB];
        if (t < RPB) {
            s_tgt[t] = targets[(row0 + t) & (N_ROWS - 1)];
            s_cnt[t] = 0;
        }
        __syncthreads();

        // Counts: one coalesced pass over targets, 8 compares per value
        int c[RPB];
        #pragma unroll
        for (int j = 0; j < RPB; ++j) c[j] = 0;
        const int t0 = s_tgt[0], t1 = s_tgt[1], t2 = s_tgt[2], t3 = s_tgt[3];
        const int t4 = s_tgt[4], t5 = s_tgt[5], t6 = s_tgt[6], t7 = s_tgt[7];
        #pragma unroll
        for (int k = 0; k < N_ROWS / 256; ++k) {   // 16 L2-hot loads
            const int v = __ldg(&targets[k * 256 + t]);
            c[0] += (v == t0); c[1] += (v == t1); c[2] += (v == t2); c[3] += (v == t3);
            c[4] += (v == t4); c[5] += (v == t5); c[6] += (v == t6); c[7] += (v == t7);
        }
        #pragma unroll
        for (int j = 0; j < RPB; ++j)
            c[j] = __reduce_add_sync(0xFFFFFFFFu, c[j]);   // REDUX.SUM
        if ((t & 31) == 0) {
            #pragma unroll
            for (int j = 0; j < RPB; ++j) atomicAdd(&s_cnt[j], c[j]);
        }
        __syncthreads();

        if (t < RPB) {
            const int r  = row0 + t;
            const int i  = r & (N_ROWS - 1);       // element index for PRNG
            const int pc = s_cnt[t];
            int      cnt;
            uint32_t key;
            if (r < N_ROWS) { cnt = pc; key = 1u; }     // positives: key(1)
            else {
                cnt = N_ROWS - pc;
                if (cnt < 1) cnt = 1;
                key = 2u;                                // negatives: key(2)
            }
            const float u = bits_to_uniform(jax_bits32(key, (uint32_t)i));
            int idx = (int)(u * (float)cnt);             // f32 mul + trunc
            if (idx > cnt - 1) idx = cnt - 1;
            s_src[t] = idx;
        }
        __syncthreads();

        float4* base = out + (size_t)2 * N_ROWS * ROW_F4;  // start of pair2
        #pragma unroll
        for (int rp = 0; rp < RPB / 2; ++rp) {
            const int r0 = row0 + rp * 2;
            copy2(in + (size_t)s_src[rp * 2]     * ROW_F4,
                  in + (size_t)s_src[rp * 2 + 1] * ROW_F4,
                  base + (size_t)r0       * ROW_F4,
                  base + (size_t)(r0 + 1) * ROW_F4, t);
        }
    } else {
        // ---------------- pair1: dual store ----------------
        const int p    = b - P2_BLOCKS;
        const int row0 = p * RPB;                  // input row in [0, 4096)
        #pragma unroll
        for (int rr = 0; rr < RPB; rr += 2) {
            const int r0 = row0 + rr;
            const int r1 = r0 + 1;
            const float4* s0 = in + (size_t)r0 * ROW_F4;
            const float4* s1 = in + (size_t)r1 * ROW_F4;
            const float4 a0 = __ldg(s0 + t);
            const float4 a1 = __ldg(s0 + t + 256);
            const float4 b0 = __ldg(s1 + t);
            const float4 b1 = __ldg(s1 + t + 256);
            float4* dA0 = out + (size_t)r0 * ROW_F4;
            float4* dB0 = out + (size_t)(r0 + N_ROWS) * ROW_F4;
            float4* dA1 = out + (size_t)r1 * ROW_F4;
            float4* dB1 = out + (size_t)(r1 + N_ROWS) * ROW_F4;
            __stcs(dA0 + t,       a0); __stcs(dA0 + t + 256, a1);
            __stcs(dB0 + t,       a0); __stcs(dB0 + t + 256, a1);
            __stcs(dA1 + t,       b0); __stcs(dA1 + t + 256, b1);
            __stcs(dB1 + t,       b0); __stcs(dB1 + t + 256, b1);
        }
        // y = [1]*n ++ [0]*n : 512 floats per block for the first 16 blocks
        if (p < 16) {
            const int base = p * 512;
            y_out[base + t]       = (base + t       < N_ROWS) ? 1.0f : 0.0f;
            y_out[base + 256 + t] = (base + 256 + t < N_ROWS) ? 1.0f : 0.0f;
        }
    }
}

// ---------------------------------------------------------------------------
// kernel_launch: inputs = d_in[0] (f32 4096x2048), targets = d_in[1] (i32 4096)
// out layout (flat f32): pair1 [2n*d] | pair2 [2n*d] | y [2n]
// ---------------------------------------------------------------------------
extern "C" void kernel_launch(void* const* d_in, const int* in_sizes, int n_in,
                              void* d_out, int out_size) {
    (void)in_sizes; (void)n_in; (void)out_size;
    const float* inputs  = (const float*)d_in[0];
    const int*   targets = (const int*)d_in[1];
    float*       out     = (float*)d_out;
    float*       y       = out + (size_t)4 * N_ROWS * DCOLS;  // after pair1|pair2

    fused_kernel<<<P2_BLOCKS + P1_BLOCKS, 256>>>(
        (const float4*)inputs, targets, (float4*)out, y);
}